// round 1
// baseline (speedup 1.0000x reference)
#include <cuda_runtime.h>
#include <cuda_bf16.h>

// Problem constants
#define BATCH   8
#define SEQ     1024
#define DIM     768
#define HEADS   12
#define HDIM    64
#define INNER   768          // HEADS*HDIM
#define TRIPLE  2304         // 3*INNER
#define SCALE   0.125f       // 1/sqrt(64)

// ---------------- static scratch (no allocations allowed) ----------------
__device__ float g_q[BATCH * HEADS * SEQ * HDIM];     // [b,h,n,d]  25MB
__device__ float g_k[BATCH * HEADS * SEQ * HDIM];
__device__ float g_v[BATCH * HEADS * SEQ * HDIM];
__device__ float g_s[BATCH * HEADS * SEQ * SEQ];      // [b,h,n,m]  402MB
__device__ float g_rmax[BATCH * SEQ * SEQ];           // [b,n,m]    33.5MB
__device__ float g_rsuminv[BATCH * SEQ * SEQ];        // [b,n,m]
__device__ float g_o[BATCH * SEQ * INNER];            // [b,n,h*d]  25MB

// =========================================================================
// K1: QKV GEMM.  C[r][c] = sum_k x[r][k] * w_qkv[k][c]
//     r in [0, 8192) = b*1024+n ; c in [0, 2304)
//     epilogue scatters into g_q/g_k/g_v with [b,h,n,d] layout.
// 64x64 tile, BK=32, 256 threads, 4x4 per thread.
// =========================================================================
__global__ __launch_bounds__(256) void qkv_gemm_kernel(
    const float* __restrict__ x, const float* __restrict__ w)
{
    __shared__ float As[32][65];   // As[k][m]
    __shared__ float Bs[32][64];   // Bs[k][n]

    const int bm = blockIdx.y * 64;
    const int bn = blockIdx.x * 64;
    const int tid = threadIdx.x;
    const int tm = (tid >> 4) << 2;   // 0..60
    const int tn = (tid & 15) << 2;   // 0..60

    float acc[4][4] = {};

    for (int k0 = 0; k0 < DIM; k0 += 32) {
        #pragma unroll
        for (int i = tid; i < 64 * 32; i += 256) {
            int m = i >> 5, k = i & 31;
            As[k][m] = x[(size_t)(bm + m) * DIM + k0 + k];
        }
        #pragma unroll
        for (int i = tid; i < 32 * 64; i += 256) {
            int k = i >> 6, n = i & 63;
            Bs[k][n] = w[(size_t)(k0 + k) * TRIPLE + bn + n];
        }
        __syncthreads();

        #pragma unroll
        for (int k = 0; k < 32; k++) {
            float a[4], b[4];
            #pragma unroll
            for (int i = 0; i < 4; i++) a[i] = As[k][tm + i];
            #pragma unroll
            for (int j = 0; j < 4; j++) b[j] = Bs[k][tn + j];
            #pragma unroll
            for (int i = 0; i < 4; i++)
                #pragma unroll
                for (int j = 0; j < 4; j++)
                    acc[i][j] = fmaf(a[i], b[j], acc[i][j]);
        }
        __syncthreads();
    }

    // epilogue: scatter to q/k/v head-major layout
    #pragma unroll
    for (int i = 0; i < 4; i++) {
        int r = bm + tm + i;
        int b = r >> 10, n = r & 1023;
        #pragma unroll
        for (int j = 0; j < 4; j++) {
            int c = bn + tn + j;
            int chunk = c / INNER;           // 0=q,1=k,2=v
            int e = c % INNER;
            int h = e >> 6, d = e & 63;
            float* dst = (chunk == 0) ? g_q : (chunk == 1 ? g_k : g_v);
            dst[(((b * HEADS + h) * SEQ) + n) * HDIM + d] = acc[i][j];
        }
    }
}

// =========================================================================
// K2: scores  S[b,h,n,m] = SCALE * sum_d Q[b,h,n,d] * K[b,h,m,d]
// one CTA: 64(n) x 64(m) tile for one (b,h). K-dim (64) fully resident.
// Q/K stored transposed in smem [d][row], pad 65 -> conflict-free.
// =========================================================================
__global__ __launch_bounds__(256) void score_kernel()
{
    __shared__ float Qs[64][65];   // [d][n]
    __shared__ float Ks[64][65];   // [d][m]

    const int bh = blockIdx.z;             // 0..95
    const int n0 = blockIdx.y * 64;
    const int m0 = blockIdx.x * 64;
    const int tid = threadIdx.x;
    const int tm = (tid >> 4) << 2;   // n offset
    const int tn = (tid & 15) << 2;   // m offset

    const float* qbase = g_q + ((size_t)bh * SEQ + n0) * HDIM;
    const float* kbase = g_k + ((size_t)bh * SEQ + m0) * HDIM;

    for (int i = tid; i < 64 * 64; i += 256) {
        int r = i >> 6, d = i & 63;
        Qs[d][r] = qbase[r * HDIM + d];
        Ks[d][r] = kbase[r * HDIM + d];
    }
    __syncthreads();

    float acc[4][4] = {};
    #pragma unroll
    for (int d = 0; d < 64; d++) {
        float a[4], b[4];
        #pragma unroll
        for (int i = 0; i < 4; i++) a[i] = Qs[d][tm + i];
        #pragma unroll
        for (int j = 0; j < 4; j++) b[j] = Ks[d][tn + j];
        #pragma unroll
        for (int i = 0; i < 4; i++)
            #pragma unroll
            for (int j = 0; j < 4; j++)
                acc[i][j] = fmaf(a[i], b[j], acc[i][j]);
    }

    float* sbase = g_s + ((size_t)bh * SEQ) * SEQ;
    #pragma unroll
    for (int i = 0; i < 4; i++) {
        int n = n0 + tm + i;
        #pragma unroll
        for (int j = 0; j < 4; j++) {
            sbase[(size_t)n * SEQ + m0 + tn + j] = acc[i][j] * SCALE;
        }
    }
}

// =========================================================================
// K3: softmax-over-heads statistics. For each (b,n,m): max_h and 1/sum_h exp.
// =========================================================================
__global__ __launch_bounds__(256) void hsoftmax_stats_kernel()
{
    int idx = blockIdx.x * 256 + threadIdx.x;   // < 8*1024*1024
    int m = idx & 1023;
    int n = (idx >> 10) & 1023;
    int b = idx >> 20;

    float v[HEADS];
    float mx = -1e30f;
    #pragma unroll
    for (int h = 0; h < HEADS; h++) {
        v[h] = g_s[(((size_t)(b * HEADS + h) * SEQ) + n) * SEQ + m];
        mx = fmaxf(mx, v[h]);
    }
    float s = 0.0f;
    #pragma unroll
    for (int h = 0; h < HEADS; h++) s += __expf(v[h] - mx);

    g_rmax[idx] = mx;
    g_rsuminv[idx] = 1.0f / s;
}

// =========================================================================
// K4: O[b,h,n,d] = sum_m P[b,h,n,m] * V[b,h,m,d]
//     P computed on the fly: exp(S - rmax) * rsuminv
// CTA: 64(n) x 64(d, full) for one (b,h); m loop in tiles of 16.
// Output written directly in [b, n, (h,d)] layout for K5.
// =========================================================================
__global__ __launch_bounds__(256) void av_kernel()
{
    __shared__ float Ps[16][65];   // [m][n]
    __shared__ float Vs[16][64];   // [m][d]

    const int bh = blockIdx.z;
    const int b = bh / HEADS, h = bh % HEADS;
    const int n0 = blockIdx.y * 64;
    const int tid = threadIdx.x;
    const int tm = (tid >> 4) << 2;   // n offset
    const int tn = (tid & 15) << 2;   // d offset

    float acc[4][4] = {};

    const float* srow = g_s + ((size_t)bh * SEQ + n0) * SEQ;
    const float* mrow = g_rmax + ((size_t)b * SEQ + n0) * SEQ;
    const float* zrow = g_rsuminv + ((size_t)b * SEQ + n0) * SEQ;
    const float* vbase = g_v + (size_t)bh * SEQ * HDIM;

    for (int m0 = 0; m0 < SEQ; m0 += 16) {
        #pragma unroll
        for (int i = tid; i < 64 * 16; i += 256) {
            int n = i >> 4, m = i & 15;
            size_t off = (size_t)n * SEQ + m0 + m;
            float s = srow[off];
            float mx = mrow[off];
            float rz = zrow[off];
            Ps[m][n] = __expf(s - mx) * rz;
        }
        #pragma unroll
        for (int i = tid; i < 16 * 64; i += 256) {
            int m = i >> 6, d = i & 63;
            Vs[m][d] = vbase[(size_t)(m0 + m) * HDIM + d];
        }
        __syncthreads();

        #pragma unroll
        for (int mm = 0; mm < 16; mm++) {
            float a[4], v4[4];
            #pragma unroll
            for (int i = 0; i < 4; i++) a[i] = Ps[mm][tm + i];
            #pragma unroll
            for (int j = 0; j < 4; j++) v4[j] = Vs[mm][tn + j];
            #pragma unroll
            for (int i = 0; i < 4; i++)
                #pragma unroll
                for (int j = 0; j < 4; j++)
                    acc[i][j] = fmaf(a[i], v4[j], acc[i][j]);
        }
        __syncthreads();
    }

    // write as [b, n, h*64 + d]
    #pragma unroll
    for (int i = 0; i < 4; i++) {
        int n = n0 + tm + i;
        #pragma unroll
        for (int j = 0; j < 4; j++) {
            int d = tn + j;
            g_o[((size_t)(b * SEQ + n) * INNER) + h * HDIM + d] = acc[i][j];
        }
    }
}

// =========================================================================
// K5: output projection  out[r][c] = sum_k O[r][k] * w_out[k][c] + b_out[c]
// =========================================================================
__global__ __launch_bounds__(256) void oproj_kernel(
    const float* __restrict__ w, const float* __restrict__ bias,
    float* __restrict__ out)
{
    __shared__ float As[32][65];
    __shared__ float Bs[32][64];

    const int bm = blockIdx.y * 64;
    const int bn = blockIdx.x * 64;
    const int tid = threadIdx.x;
    const int tm = (tid >> 4) << 2;
    const int tn = (tid & 15) << 2;

    float acc[4][4] = {};

    for (int k0 = 0; k0 < INNER; k0 += 32) {
        #pragma unroll
        for (int i = tid; i < 64 * 32; i += 256) {
            int m = i >> 5, k = i & 31;
            As[k][m] = g_o[(size_t)(bm + m) * INNER + k0 + k];
        }
        #pragma unroll
        for (int i = tid; i < 32 * 64; i += 256) {
            int k = i >> 6, n = i & 63;
            Bs[k][n] = w[(size_t)(k0 + k) * DIM + bn + n];
        }
        __syncthreads();

        #pragma unroll
        for (int k = 0; k < 32; k++) {
            float a[4], b[4];
            #pragma unroll
            for (int i = 0; i < 4; i++) a[i] = As[k][tm + i];
            #pragma unroll
            for (int j = 0; j < 4; j++) b[j] = Bs[k][tn + j];
            #pragma unroll
            for (int i = 0; i < 4; i++)
                #pragma unroll
                for (int j = 0; j < 4; j++)
                    acc[i][j] = fmaf(a[i], b[j], acc[i][j]);
        }
        __syncthreads();
    }

    #pragma unroll
    for (int i = 0; i < 4; i++) {
        int r = bm + tm + i;
        #pragma unroll
        for (int j = 0; j < 4; j++) {
            int c = bn + tn + j;
            out[(size_t)r * DIM + c] = acc[i][j] + bias[c];
        }
    }
}

// =========================================================================
extern "C" void kernel_launch(void* const* d_in, const int* in_sizes, int n_in,
                              void* d_out, int out_size)
{
    const float* x     = (const float*)d_in[0];   // [8,1024,768]
    const float* w_qkv = (const float*)d_in[1];   // [768,2304]
    const float* w_out = (const float*)d_in[2];   // [768,768]
    const float* b_out = (const float*)d_in[3];   // [768]
    float* out = (float*)d_out;                   // [8,1024,768]

    // K1: QKV projection
    {
        dim3 grid(TRIPLE / 64, (BATCH * SEQ) / 64);   // 36 x 128
        qkv_gemm_kernel<<<grid, 256>>>(x, w_qkv);
    }
    // K2: scores
    {
        dim3 grid(SEQ / 64, SEQ / 64, BATCH * HEADS); // 16 x 16 x 96
        score_kernel<<<grid, 256>>>();
    }
    // K3: softmax-over-heads stats
    {
        int total = BATCH * SEQ * SEQ;                // 8M
        hsoftmax_stats_kernel<<<total / 256, 256>>>();
    }
    // K4: attention @ V
    {
        dim3 grid(1, SEQ / 64, BATCH * HEADS);        // 1 x 16 x 96
        av_kernel<<<grid, 256>>>();
    }
    // K5: output projection + bias
    {
        dim3 grid(DIM / 64, (BATCH * SEQ) / 64);      // 12 x 128
        oproj_kernel<<<grid, 256>>>(w_out, b_out, out);
    }
}

// round 2
// speedup vs baseline: 1.3346x; 1.3346x over previous
#include <cuda_runtime.h>
#include <cuda_bf16.h>

// Problem constants
#define BATCH   8
#define SEQ     1024
#define DIM     768
#define HEADS   12
#define HDIM    64
#define INNER   768          // HEADS*HDIM
#define TRIPLE  2304         // 3*INNER
#define SCALE   0.125f       // 1/sqrt(64)

// ---------------- static scratch (no allocations allowed) ----------------
__device__ float g_q[BATCH * HEADS * SEQ * HDIM];     // [b,h,n,d]
__device__ float g_k[BATCH * HEADS * SEQ * HDIM];
__device__ float g_v[BATCH * HEADS * SEQ * HDIM];
__device__ float g_s[(size_t)BATCH * HEADS * SEQ * SEQ]; // E then P in place
__device__ float g_o[BATCH * SEQ * INNER];            // [b,n,h*d]

// ---------------- packed f32x2 helpers (Blackwell sm_103a) ----------------
__device__ __forceinline__ unsigned long long pack2(float x) {
    unsigned int u = __float_as_uint(x);
    unsigned long long d;
    asm("mov.b64 %0, {%1, %1};" : "=l"(d) : "r"(u));
    return d;
}
__device__ __forceinline__ void ffma2(unsigned long long& d,
                                      unsigned long long a,
                                      unsigned long long b) {
    asm("fma.rn.f32x2 %0, %1, %2, %0;" : "+l"(d) : "l"(a), "l"(b));
}
__device__ __forceinline__ float2 unpack2(unsigned long long v) {
    unsigned int lo, hi;
    asm("mov.b64 {%0, %1}, %2;" : "=r"(lo), "=r"(hi) : "l"(v));
    return make_float2(__uint_as_float(lo), __uint_as_float(hi));
}

// ---------------- FMA-pipe exp (no MUFU), rel err ~3e-7 -------------------
__device__ __forceinline__ float fast_exp(float x) {
    const float LOG2E = 1.4426950408889634f;
    const float MAGIC = 12582912.0f;              // 1.5 * 2^23
    float z = fmaf(x, LOG2E, MAGIC);
    int   e = __float_as_int(z) - 0x4B400000;     // round-to-nearest int
    float i = z - MAGIC;
    float f = fmaf(x, LOG2E, -i);                 // f in [-0.5, 0.5]
    // 2^f via Taylor deg 6
    float p = 1.5403531e-4f;
    p = fmaf(p, f, 1.3333558e-3f);
    p = fmaf(p, f, 9.6181291e-3f);
    p = fmaf(p, f, 5.5504109e-2f);
    p = fmaf(p, f, 2.4022651e-1f);
    p = fmaf(p, f, 6.9314718e-1f);
    p = fmaf(p, f, 1.0f);
    return __int_as_float(__float_as_int(p) + (e << 23));
}

// =========================================================================
// K1: QKV GEMM.  [8192 x 2304] = x[8192 x 768] @ w[768 x 2304]
// 128x128 tile, BK=8, 256 threads, 8x8 per thread via f32x2.
// Epilogue scatters into g_q/g_k/g_v with [b,h,n,d] layout (float4 stores).
// =========================================================================
__global__ __launch_bounds__(256, 2) void qkv_gemm_kernel(
    const float* __restrict__ x, const float* __restrict__ w)
{
    __shared__ float As[2][8][128];   // [k][m] (transposed)
    __shared__ float Bs[2][8][128];   // [k][n]

    const int bm = blockIdx.y * 128;
    const int bn = blockIdx.x * 128;
    const int tid = threadIdx.x;
    const int ty = tid >> 4, tx = tid & 15;
    const int r0 = ty * 4, r1 = r0 + 64;
    const int c0 = tx * 4, c1 = c0 + 64;

    const int aRow = tid >> 1, aK = (tid & 1) * 4;
    const int bK = tid >> 5, bCol = (tid & 31) * 4;
    const float* aPtr = x + (size_t)(bm + aRow) * DIM + aK;
    const float* bPtr = w + (size_t)bK * TRIPLE + bn + bCol;

    float4 av = *(const float4*)aPtr;
    float4 bv = *(const float4*)bPtr;
    As[0][aK + 0][aRow] = av.x; As[0][aK + 1][aRow] = av.y;
    As[0][aK + 2][aRow] = av.z; As[0][aK + 3][aRow] = av.w;
    *(float4*)&Bs[0][bK][bCol] = bv;
    __syncthreads();

    unsigned long long acc[8][4] = {};
    int buf = 0;
    const int NIT = DIM / 8;  // 96

    for (int it = 0; it < NIT; ++it) {
        if (it + 1 < NIT) {
            av = *(const float4*)(aPtr + (it + 1) * 8);
            bv = *(const float4*)(bPtr + (size_t)(it + 1) * 8 * TRIPLE);
        }
        #pragma unroll
        for (int k = 0; k < 8; k++) {
            float4 a0 = *(const float4*)&As[buf][k][r0];
            float4 a1 = *(const float4*)&As[buf][k][r1];
            ulonglong2 b0 = *(const ulonglong2*)&Bs[buf][k][c0];
            ulonglong2 b1 = *(const ulonglong2*)&Bs[buf][k][c1];
            float ar[8] = {a0.x, a0.y, a0.z, a0.w, a1.x, a1.y, a1.z, a1.w};
            #pragma unroll
            for (int i = 0; i < 8; i++) {
                unsigned long long ap = pack2(ar[i]);
                ffma2(acc[i][0], ap, b0.x);
                ffma2(acc[i][1], ap, b0.y);
                ffma2(acc[i][2], ap, b1.x);
                ffma2(acc[i][3], ap, b1.y);
            }
        }
        if (it + 1 < NIT) {
            buf ^= 1;
            As[buf][aK + 0][aRow] = av.x; As[buf][aK + 1][aRow] = av.y;
            As[buf][aK + 2][aRow] = av.z; As[buf][aK + 3][aRow] = av.w;
            *(float4*)&Bs[buf][bK][bCol] = bv;
            __syncthreads();
        }
    }

    #pragma unroll
    for (int i = 0; i < 8; i++) {
        int r = bm + ((i < 4) ? (r0 + i) : (r1 + i - 4));
        int b = r >> 10, n = r & 1023;
        #pragma unroll
        for (int jq = 0; jq < 2; jq++) {
            int c = bn + (jq ? c1 : c0);
            float2 p0 = unpack2(acc[i][jq * 2 + 0]);
            float2 p1 = unpack2(acc[i][jq * 2 + 1]);
            float4 val = make_float4(p0.x, p0.y, p1.x, p1.y);
            int chunk = c / INNER;
            int e = c % INNER;
            int h = e >> 6, d = e & 63;
            float* dst = (chunk == 0) ? g_q : (chunk == 1 ? g_k : g_v);
            *(float4*)&dst[(((size_t)(b * HEADS + h) * SEQ) + n) * HDIM + d] = val;
        }
    }
}

// =========================================================================
// K2: scores+exp.  E[b,h,n,m] = exp(SCALE * Q[b,h,n,:] . K[b,h,m,:])
// 128(n) x 128(m) tile per (b,h); K-dim 64 in 8 BK=8 steps.
// Both operands transpose-loaded into smem.
// =========================================================================
__global__ __launch_bounds__(256, 2) void score_kernel()
{
    __shared__ float As[2][8][128];   // Q: [d][n]
    __shared__ float Bs[2][8][128];   // K: [d][m]

    const int bh = blockIdx.z;
    const int n0 = blockIdx.y * 128;
    const int m0 = blockIdx.x * 128;
    const int tid = threadIdx.x;
    const int ty = tid >> 4, tx = tid & 15;
    const int r0 = ty * 4, r1 = r0 + 64;
    const int c0 = tx * 4, c1 = c0 + 64;

    const int aRow = tid >> 1, aK = (tid & 1) * 4;
    const float* aPtr = g_q + ((size_t)bh * SEQ + n0 + aRow) * HDIM + aK;
    const float* bPtr = g_k + ((size_t)bh * SEQ + m0 + aRow) * HDIM + aK;

    float4 av = *(const float4*)aPtr;
    float4 bv = *(const float4*)bPtr;
    As[0][aK + 0][aRow] = av.x; As[0][aK + 1][aRow] = av.y;
    As[0][aK + 2][aRow] = av.z; As[0][aK + 3][aRow] = av.w;
    Bs[0][aK + 0][aRow] = bv.x; Bs[0][aK + 1][aRow] = bv.y;
    Bs[0][aK + 2][aRow] = bv.z; Bs[0][aK + 3][aRow] = bv.w;
    __syncthreads();

    unsigned long long acc[8][4] = {};
    int buf = 0;
    const int NIT = HDIM / 8;  // 8

    for (int it = 0; it < NIT; ++it) {
        if (it + 1 < NIT) {
            av = *(const float4*)(aPtr + (it + 1) * 8);
            bv = *(const float4*)(bPtr + (it + 1) * 8);
        }
        #pragma unroll
        for (int k = 0; k < 8; k++) {
            float4 a0 = *(const float4*)&As[buf][k][r0];
            float4 a1 = *(const float4*)&As[buf][k][r1];
            ulonglong2 b0 = *(const ulonglong2*)&Bs[buf][k][c0];
            ulonglong2 b1 = *(const ulonglong2*)&Bs[buf][k][c1];
            float ar[8] = {a0.x, a0.y, a0.z, a0.w, a1.x, a1.y, a1.z, a1.w};
            #pragma unroll
            for (int i = 0; i < 8; i++) {
                unsigned long long ap = pack2(ar[i]);
                ffma2(acc[i][0], ap, b0.x);
                ffma2(acc[i][1], ap, b0.y);
                ffma2(acc[i][2], ap, b1.x);
                ffma2(acc[i][3], ap, b1.y);
            }
        }
        if (it + 1 < NIT) {
            buf ^= 1;
            As[buf][aK + 0][aRow] = av.x; As[buf][aK + 1][aRow] = av.y;
            As[buf][aK + 2][aRow] = av.z; As[buf][aK + 3][aRow] = av.w;
            Bs[buf][aK + 0][aRow] = bv.x; Bs[buf][aK + 1][aRow] = bv.y;
            Bs[buf][aK + 2][aRow] = bv.z; Bs[buf][aK + 3][aRow] = bv.w;
            __syncthreads();
        }
    }

    #pragma unroll
    for (int i = 0; i < 8; i++) {
        int n = n0 + ((i < 4) ? (r0 + i) : (r1 + i - 4));
        float* srow = g_s + ((size_t)bh * SEQ + n) * SEQ;
        #pragma unroll
        for (int jq = 0; jq < 2; jq++) {
            int m = m0 + (jq ? c1 : c0);
            float2 p0 = unpack2(acc[i][jq * 2 + 0]);
            float2 p1 = unpack2(acc[i][jq * 2 + 1]);
            float4 val = make_float4(fast_exp(p0.x * SCALE), fast_exp(p0.y * SCALE),
                                     fast_exp(p1.x * SCALE), fast_exp(p1.y * SCALE));
            *(float4*)&srow[m] = val;
        }
    }
}

// =========================================================================
// K3: normalize over heads in place: P = E / sum_h E. float4 along m.
// =========================================================================
__global__ __launch_bounds__(256) void norm_kernel()
{
    size_t idx = (size_t)blockIdx.x * 256 + threadIdx.x;  // < 2M
    int m4 = idx & 255;
    int n = (idx >> 8) & 1023;
    int b = (int)(idx >> 18);

    float4* base = (float4*)g_s;
    float4 v[HEADS];
    float4 s = make_float4(0.f, 0.f, 0.f, 0.f);
    #pragma unroll
    for (int h = 0; h < HEADS; h++) {
        size_t off = ((size_t)(b * HEADS + h) * SEQ + n) * (SEQ / 4) + m4;
        v[h] = base[off];
        s.x += v[h].x; s.y += v[h].y; s.z += v[h].z; s.w += v[h].w;
    }
    float rx = 1.0f / s.x, ry = 1.0f / s.y, rz = 1.0f / s.z, rw = 1.0f / s.w;
    #pragma unroll
    for (int h = 0; h < HEADS; h++) {
        size_t off = ((size_t)(b * HEADS + h) * SEQ + n) * (SEQ / 4) + m4;
        float4 p = v[h];
        p.x *= rx; p.y *= ry; p.z *= rz; p.w *= rw;
        base[off] = p;
    }
}

// =========================================================================
// K4: O = P @ V per (b,h).  M=1024(n), N=64(d), K=1024(m).
// 128x64 tile, BK=8, 256 threads, 8x4 per thread via f32x2.
// Output written as [b, n, (h d)].
// =========================================================================
__global__ __launch_bounds__(256, 2) void av_kernel()
{
    __shared__ float As[2][8][128];   // P: [m][n] (transposed)
    __shared__ float Bs[2][8][64];    // V: [m][d]

    const int n0 = blockIdx.x * 128;
    const int bh = blockIdx.y;
    const int b = bh / HEADS, h = bh % HEADS;
    const int tid = threadIdx.x;
    const int ty = tid >> 4, tx = tid & 15;
    const int r0 = ty * 4, r1 = r0 + 64;
    const int c0 = tx * 4;

    const int aRow = tid >> 1, aK = (tid & 1) * 4;
    const float* aPtr = g_s + ((size_t)bh * SEQ + n0 + aRow) * SEQ + aK;
    const int bK = tid >> 4, bCol = (tid & 15) * 4;   // tid<128 only
    const float* bPtr = g_v + (size_t)bh * SEQ * HDIM + (size_t)bK * HDIM + bCol;

    float4 av = *(const float4*)aPtr;
    float4 bv = make_float4(0.f, 0.f, 0.f, 0.f);
    if (tid < 128) bv = *(const float4*)bPtr;
    As[0][aK + 0][aRow] = av.x; As[0][aK + 1][aRow] = av.y;
    As[0][aK + 2][aRow] = av.z; As[0][aK + 3][aRow] = av.w;
    if (tid < 128) *(float4*)&Bs[0][bK][bCol] = bv;
    __syncthreads();

    unsigned long long acc[8][2] = {};
    int buf = 0;
    const int NIT = SEQ / 8;  // 128

    for (int it = 0; it < NIT; ++it) {
        if (it + 1 < NIT) {
            av = *(const float4*)(aPtr + (it + 1) * 8);
            if (tid < 128) bv = *(const float4*)(bPtr + (size_t)(it + 1) * 8 * HDIM);
        }
        #pragma unroll
        for (int k = 0; k < 8; k++) {
            float4 a0 = *(const float4*)&As[buf][k][r0];
            float4 a1 = *(const float4*)&As[buf][k][r1];
            ulonglong2 b2 = *(const ulonglong2*)&Bs[buf][k][c0];
            float ar[8] = {a0.x, a0.y, a0.z, a0.w, a1.x, a1.y, a1.z, a1.w};
            #pragma unroll
            for (int i = 0; i < 8; i++) {
                unsigned long long ap = pack2(ar[i]);
                ffma2(acc[i][0], ap, b2.x);
                ffma2(acc[i][1], ap, b2.y);
            }
        }
        if (it + 1 < NIT) {
            buf ^= 1;
            As[buf][aK + 0][aRow] = av.x; As[buf][aK + 1][aRow] = av.y;
            As[buf][aK + 2][aRow] = av.z; As[buf][aK + 3][aRow] = av.w;
            if (tid < 128) *(float4*)&Bs[buf][bK][bCol] = bv;
            __syncthreads();
        }
    }

    #pragma unroll
    for (int i = 0; i < 8; i++) {
        int n = n0 + ((i < 4) ? (r0 + i) : (r1 + i - 4));
        float2 p0 = unpack2(acc[i][0]);
        float2 p1 = unpack2(acc[i][1]);
        float4 val = make_float4(p0.x, p0.y, p1.x, p1.y);
        *(float4*)&g_o[((size_t)(b * SEQ + n)) * INNER + h * HDIM + c0] = val;
    }
}

// =========================================================================
// K5: output projection. [8192 x 768] = O[8192 x 768] @ w_out[768 x 768] + b
// =========================================================================
__global__ __launch_bounds__(256, 2) void oproj_kernel(
    const float* __restrict__ w, const float* __restrict__ bias,
    float* __restrict__ out)
{
    __shared__ float As[2][8][128];
    __shared__ float Bs[2][8][128];

    const int bm = blockIdx.y * 128;
    const int bn = blockIdx.x * 128;
    const int tid = threadIdx.x;
    const int ty = tid >> 4, tx = tid & 15;
    const int r0 = ty * 4, r1 = r0 + 64;
    const int c0 = tx * 4, c1 = c0 + 64;

    const int aRow = tid >> 1, aK = (tid & 1) * 4;
    const int bK = tid >> 5, bCol = (tid & 31) * 4;
    const float* aPtr = g_o + (size_t)(bm + aRow) * INNER + aK;
    const float* bPtr = w + (size_t)bK * DIM + bn + bCol;

    float4 av = *(const float4*)aPtr;
    float4 bv = *(const float4*)bPtr;
    As[0][aK + 0][aRow] = av.x; As[0][aK + 1][aRow] = av.y;
    As[0][aK + 2][aRow] = av.z; As[0][aK + 3][aRow] = av.w;
    *(float4*)&Bs[0][bK][bCol] = bv;
    __syncthreads();

    unsigned long long acc[8][4] = {};
    int buf = 0;
    const int NIT = INNER / 8;  // 96

    for (int it = 0; it < NIT; ++it) {
        if (it + 1 < NIT) {
            av = *(const float4*)(aPtr + (it + 1) * 8);
            bv = *(const float4*)(bPtr + (size_t)(it + 1) * 8 * DIM);
        }
        #pragma unroll
        for (int k = 0; k < 8; k++) {
            float4 a0 = *(const float4*)&As[buf][k][r0];
            float4 a1 = *(const float4*)&As[buf][k][r1];
            ulonglong2 b0 = *(const ulonglong2*)&Bs[buf][k][c0];
            ulonglong2 b1 = *(const ulonglong2*)&Bs[buf][k][c1];
            float ar[8] = {a0.x, a0.y, a0.z, a0.w, a1.x, a1.y, a1.z, a1.w};
            #pragma unroll
            for (int i = 0; i < 8; i++) {
                unsigned long long ap = pack2(ar[i]);
                ffma2(acc[i][0], ap, b0.x);
                ffma2(acc[i][1], ap, b0.y);
                ffma2(acc[i][2], ap, b1.x);
                ffma2(acc[i][3], ap, b1.y);
            }
        }
        if (it + 1 < NIT) {
            buf ^= 1;
            As[buf][aK + 0][aRow] = av.x; As[buf][aK + 1][aRow] = av.y;
            As[buf][aK + 2][aRow] = av.z; As[buf][aK + 3][aRow] = av.w;
            *(float4*)&Bs[buf][bK][bCol] = bv;
            __syncthreads();
        }
    }

    #pragma unroll
    for (int i = 0; i < 8; i++) {
        int r = bm + ((i < 4) ? (r0 + i) : (r1 + i - 4));
        #pragma unroll
        for (int jq = 0; jq < 2; jq++) {
            int c = bn + (jq ? c1 : c0);
            float4 bq = *(const float4*)&bias[c];
            float2 p0 = unpack2(acc[i][jq * 2 + 0]);
            float2 p1 = unpack2(acc[i][jq * 2 + 1]);
            float4 val = make_float4(p0.x + bq.x, p0.y + bq.y,
                                     p1.x + bq.z, p1.y + bq.w);
            *(float4*)&out[(size_t)r * DIM + c] = val;
        }
    }
}

// =========================================================================
extern "C" void kernel_launch(void* const* d_in, const int* in_sizes, int n_in,
                              void* d_out, int out_size)
{
    const float* x     = (const float*)d_in[0];   // [8,1024,768]
    const float* w_qkv = (const float*)d_in[1];   // [768,2304]
    const float* w_out = (const float*)d_in[2];   // [768,768]
    const float* b_out = (const float*)d_in[3];   // [768]
    float* out = (float*)d_out;                   // [8,1024,768]

    // K1: QKV projection
    {
        dim3 grid(TRIPLE / 128, (BATCH * SEQ) / 128);   // 18 x 64
        qkv_gemm_kernel<<<grid, 256>>>(x, w_qkv);
    }
    // K2: scores -> exp
    {
        dim3 grid(SEQ / 128, SEQ / 128, BATCH * HEADS); // 8 x 8 x 96
        score_kernel<<<grid, 256>>>();
    }
    // K3: normalize over heads (in place)
    {
        int total = BATCH * SEQ * (SEQ / 4);            // 2M
        norm_kernel<<<total / 256, 256>>>();
    }
    // K4: attention @ V
    {
        dim3 grid(SEQ / 128, BATCH * HEADS);            // 8 x 96
        av_kernel<<<grid, 256>>>();
    }
    // K5: output projection + bias
    {
        dim3 grid(DIM / 128, (BATCH * SEQ) / 128);      // 6 x 64
        oproj_kernel<<<grid, 256>>>(w_out, b_out, out);
    }
}